// round 14
// baseline (speedup 1.0000x reference)
#include <cuda_runtime.h>
#include <cuda_bf16.h>
#include <cuda_fp16.h>
#include <math.h>
#include <stdint.h>

// Problem constants
#define BATCH 4
#define TLEN 1024
#define EMB 512
#define VOC 50257
#define MALL (BATCH * TLEN)          // 4096 rows

// fp16 NT MMA tiling (attention path)
#define BM 128
#define BN 128
#define BKC 32                        // k per chunk (fp16) = 64B/row
#define ROWB 80                       // SMEM row stride bytes (conflict-free)
#define F16_TILE (128 * ROWB)         // 10240
#define F16_STAGE (2 * F16_TILE)      // 20480 (A + B)
#define SMEM_F16 (2 * F16_STAGE)      // 40960 -> 2 CTAs/SM

// lm_head fp16 tiling (256 threads, warp tile 64x64)
#define LM_BM 128
#define LM_BN 256
#define NT_N 197                      // ceil(50257/256)
#define N_PAD (NT_N * LM_BN)          // 50432
#define NKT (EMB / 16)                // 32 k-tiles of 16
#define LM_NCH (NKT / 4)              // 8 chunks
#define SM_A_BYTES (8 * 4 * 512)      // 16384
#define SM_B_BYTES (32 * 4 * 256)     // 32768
#define LM_STAGE (SM_A_BYTES + SM_B_BYTES)   // 49152
#define SMEM_LM (2 * LM_STAGE)        // 98304

// buffers
static __device__ __half    g_Xf[MALL * EMB];
static __device__ __half    g_Wtf[3 * EMB * EMB];        // [Wk^T,Wq^T,Wv^T] fp16
static __device__ __half    g_KQVf[3 * MALL * EMB];
static __device__ __half    g_Vtf[MALL * EMB];           // V^T per batch
static __device__ float     g_WEI[BATCH * TLEN * TLEN];
static __device__ __half    g_ATTf[BATCH * TLEN * TLEN];
static __device__ uint32_t  g_Apack[MALL * EMB / 2];     // frag-major fp16x2
static __device__ uint32_t  g_Bpack[(size_t)N_PAD * EMB / 2];
static __device__ float  g_cmax[BATCH * TLEN];
static __device__ float  g_csum[BATCH * TLEN];
static __device__ float  g_rowloss[MALL];
static __device__ float2 g_P[(size_t)MALL * NT_N];
static __device__ float2 g_CP[(size_t)BATCH * TLEN * 8]; // col-softmax partials

// ============================================================================
// PTX helpers
// ============================================================================
__device__ __forceinline__ uint32_t smem_u32(const void* p) {
    uint32_t a;
    asm("{ .reg .u64 t; cvta.to.shared.u64 t, %1; cvt.u32.u64 %0, t; }"
        : "=r"(a) : "l"(p));
    return a;
}
__device__ __forceinline__ void cp_async16(uint32_t dst, const void* src) {
    asm volatile("cp.async.cg.shared.global [%0], [%1], 16;"
                 :: "r"(dst), "l"(src) : "memory");
}
__device__ __forceinline__ void cp_commit() {
    asm volatile("cp.async.commit_group;" ::: "memory");
}
template <int N>
__device__ __forceinline__ void cp_wait() {
    asm volatile("cp.async.wait_group %0;" :: "n"(N) : "memory");
}
__device__ __forceinline__ void ldm_x4(uint32_t* r, uint32_t addr) {
    asm volatile("ldmatrix.sync.aligned.m8n8.x4.shared.b16 {%0,%1,%2,%3}, [%4];"
                 : "=r"(r[0]), "=r"(r[1]), "=r"(r[2]), "=r"(r[3]) : "r"(addr));
}
__device__ __forceinline__ void mma16816_f16(float* c, const uint32_t* a,
                                             uint32_t b0, uint32_t b1) {
    asm volatile(
        "mma.sync.aligned.m16n8k16.row.col.f32.f16.f16.f32 "
        "{%0,%1,%2,%3}, {%4,%5,%6,%7}, {%8,%9}, {%0,%1,%2,%3};"
        : "+f"(c[0]), "+f"(c[1]), "+f"(c[2]), "+f"(c[3])
        : "r"(a[0]), "r"(a[1]), "r"(a[2]), "r"(a[3]), "r"(b0), "r"(b1));
}
__device__ __forceinline__ uint32_t pack_h2(float x, float y) {
    __half2 h = __floats2half2_rn(x, y);
    return *(uint32_t*)&h;
}
__device__ __forceinline__ void lse_merge(float& m, float& l, float m2, float l2) {
    if (l2 > 0.f) {
        if (l == 0.f) { m = m2; l = l2; }
        else {
            float nm = fmaxf(m, m2);
            l = l * __expf(m - nm) + l2 * __expf(m2 - nm);
            m = nm;
        }
    }
}

// ============================================================================
// Embedding: x = tok_emb[idx] + pos_emb -> fp16
// ============================================================================
__global__ void embed_kernel(const int* __restrict__ idx,
                             const float* __restrict__ tok,
                             const float* __restrict__ pos,
                             __half* __restrict__ xf) {
    int n = blockIdx.x;
    int t = n & (TLEN - 1);
    int e4 = threadIdx.x;
    int token = __ldg(&idx[n]);
    float4 a = *(const float4*)&tok[(size_t)token * EMB + e4 * 4];
    float4 p = *(const float4*)&pos[(size_t)t * EMB + e4 * 4];
    a.x += p.x; a.y += p.y; a.z += p.z; a.w += p.w;
    uint32_t* o = (uint32_t*)(xf + (size_t)n * EMB + e4 * 4);
    o[0] = pack_h2(a.x, a.y);
    o[1] = pack_h2(a.z, a.w);
}

// z-batched: fp32 W[z] [K,N] -> transposed fp16 [N,K] at out + z*EMB*EMB
__global__ void transpose_w_kernel(const float* __restrict__ W0,
                                   const float* __restrict__ W1,
                                   const float* __restrict__ W2,
                                   __half* __restrict__ out) {
    __shared__ float t[32][33];
    const float* W = (blockIdx.z == 0) ? W0 : (blockIdx.z == 1) ? W1 : W2;
    out += (size_t)blockIdx.z * EMB * EMB;
    int n0 = blockIdx.x * 32;
    int k0 = blockIdx.y * 32;
    for (int r = threadIdx.y; r < 32; r += 8)
        t[r][threadIdx.x] = W[(size_t)(k0 + r) * EMB + n0 + threadIdx.x];
    __syncthreads();
    for (int r = threadIdx.y; r < 32; r += 8)
        out[(size_t)(n0 + r) * EMB + k0 + threadIdx.x] = __float2half(t[threadIdx.x][r]);
}

// fp16 [rows, cols] -> [cols, rows] per batch z
__global__ void transpose_h_kernel(const __half* __restrict__ src,
                                   __half* __restrict__ dst,
                                   int rows, int cols) {
    __shared__ __half t[32][33];
    src += (size_t)blockIdx.z * rows * cols;
    dst += (size_t)blockIdx.z * rows * cols;
    int c0 = blockIdx.x * 32;
    int r0 = blockIdx.y * 32;
    for (int r = threadIdx.y; r < 32; r += 8)
        t[r][threadIdx.x] = src[(size_t)(r0 + r) * cols + c0 + threadIdx.x];
    __syncthreads();
    for (int r = threadIdx.y; r < 32; r += 8)
        dst[(size_t)(c0 + r) * rows + r0 + threadIdx.x] = t[threadIdx.x][r];
}

// ============================================================================
// W_lm [512, VOC] -> Bpack frag-major fp16 [nt][kt(32)][64 u32]
// ============================================================================
__global__ void pack_w_kernel(const float* __restrict__ W,
                              uint32_t* __restrict__ Bp) {
    __shared__ float t[64][65];
    int n0 = blockIdx.x * 64;
    int k0 = blockIdx.y * 64;
    int tid = threadIdx.x;
#pragma unroll
    for (int w = 0; w < 16; ++w) {
        int e = tid + w * 256;
        int kk = e >> 6, nn = e & 63;
        int n = n0 + nn;
        t[kk][nn] = (n < VOC) ? W[(size_t)(k0 + kk) * VOC + n] : 0.f;
    }
    __syncthreads();
#pragma unroll
    for (int w = 0; w < 8; ++w) {
        int f = tid + w * 256;              // 0..2047
        int blk = f >> 6, pos = f & 63;
        int bnt = blk >> 2, bkt = blk & 3;
        int lane = pos >> 1, j = pos & 1;
        int n_loc = bnt * 8 + (lane >> 2);
        int k_loc = bkt * 16 + (lane & 3) * 2 + j * 8;
        uint32_t v = pack_h2(t[k_loc][n_loc], t[k_loc + 1][n_loc]);
        size_t addr = (size_t)(n0 / 8 + bnt) * (NKT * 64)
                    + (size_t)(k0 / 16 + bkt) * 64 + pos;
        Bp[addr] = v;
    }
}

// ============================================================================
// fp16 single-pass NT MMA GEMM: C = alpha * A @ B^T
// OM=0: fp32 out; OM=1: fp16 row-major out; OM=2: A-fragment out (to Apack)
// OM=3: fp32 out + fused causal column-softmax partials (q@k^T)
// ============================================================================
template <int OM>
__global__ __launch_bounds__(256, 2)
void mma_f16_kernel(const __half* __restrict__ A, int lda, long long sA,
                    const __half* __restrict__ B, int ldb, long long sB,
                    int nchunk, float alpha,
                    float* __restrict__ Cf, __half* __restrict__ Ch,
                    int ldc, long long sC,
                    uint32_t* __restrict__ Ap,
                    float2* __restrict__ CP) {
    extern __shared__ char smem[];
    const uint32_t sbase = smem_u32(smem);
    const int tid = threadIdx.x;
    const int wid = tid >> 5;
    const int lane = tid & 31;
    const int m0 = blockIdx.y * BM;
    const int n0 = blockIdx.x * BN;
    const int z = blockIdx.z;
    const int wm = (wid >> 2) * 64;
    const int wn = (wid & 3) * 32;

    const __half* srcA = A + (long long)z * sA + (size_t)m0 * lda;
    const __half* srcB = B + (long long)z * sB + (size_t)n0 * ldb;

    float acc[4][4][4];
#pragma unroll
    for (int i = 0; i < 4; ++i)
#pragma unroll
        for (int j = 0; j < 4; ++j)
#pragma unroll
            for (int q = 0; q < 4; ++q) acc[i][j][q] = 0.f;

    auto issue = [&](int chunk, int stage) {
#pragma unroll
        for (int j = 0; j < 4; ++j) {
            int idx = tid + j * 256;
            int t = idx >> 9;                  // 0=A, 1=B
            int r = (idx >> 2) & 127;
            int c = idx & 3;
            const __half* s = (t == 0)
                ? srcA + (size_t)r * lda + chunk * BKC + c * 8
                : srcB + (size_t)r * ldb + chunk * BKC + c * 8;
            uint32_t d = sbase + stage * F16_STAGE + t * F16_TILE + r * ROWB + c * 16;
            cp_async16(d, s);
        }
        cp_commit();
    };

    issue(0, 0);
    if (nchunk > 1) issue(1, 1);

    const int lrow = lane & 15;
    const int lcolhalf = (lane >> 4) * 16;

    for (int c = 0; c < nchunk; ++c) {
        if (c + 2 < nchunk) cp_wait<1>(); else cp_wait<0>();
        __syncthreads();

        uint32_t stg = sbase + (c & 1) * F16_STAGE;
#pragma unroll
        for (int ks = 0; ks < 2; ++ks) {
            uint32_t kb = ks * 32 + lcolhalf;
            uint32_t aF[4][4], bF[2][4];
#pragma unroll
            for (int mi = 0; mi < 4; ++mi)
                ldm_x4(aF[mi], stg + (wm + mi * 16 + lrow) * ROWB + kb);
#pragma unroll
            for (int g = 0; g < 2; ++g)
                ldm_x4(bF[g], stg + F16_TILE + (wn + g * 16 + lrow) * ROWB + kb);
#pragma unroll
            for (int mi = 0; mi < 4; ++mi)
#pragma unroll
                for (int nj = 0; nj < 4; ++nj) {
                    int g = nj >> 1, p = nj & 1;
                    mma16816_f16(acc[mi][nj], aF[mi], bF[g][p], bF[g][p + 2]);
                }
        }
        __syncthreads();
        if (c + 2 < nchunk) issue(c + 2, c & 1);
    }

#pragma unroll
    for (int mi = 0; mi < 4; ++mi) {
#pragma unroll
        for (int nj = 0; nj < 4; ++nj) {
            float v0 = alpha * acc[mi][nj][0];
            float v1 = alpha * acc[mi][nj][1];
            float v2 = alpha * acc[mi][nj][2];
            float v3 = alpha * acc[mi][nj][3];
            int mrow = m0 + wm + mi * 16 + (lane >> 2);
            int ncol = n0 + wn + nj * 8 + (lane & 3) * 2;
            if (OM == 0 || OM == 3) {
                size_t o0 = (size_t)((long long)z * sC) + (size_t)mrow * ldc + ncol;
                *(float2*)(Cf + o0) = make_float2(v0, v1);
                *(float2*)(Cf + o0 + (size_t)8 * ldc) = make_float2(v2, v3);
            } else if (OM == 1) {
                size_t o0 = (size_t)((long long)z * sC) + (size_t)mrow * ldc + ncol;
                *(uint32_t*)(Ch + o0) = pack_h2(v0, v1);
                *(uint32_t*)(Ch + o0 + (size_t)8 * ldc) = pack_h2(v2, v3);
            } else if (OM == 2) {
                int mt = (z * TLEN + mrow - (lane >> 2)) >> 4;
                int col = n0 + wn + nj * 8;
                int kt = col >> 4;
                int jh = (col >> 3) & 1;
                size_t base = (size_t)mt * 4096 + (size_t)kt * 128 + lane * 4 + jh * 2;
                Ap[base + 0] = pack_h2(v0, v1);
                Ap[base + 1] = pack_h2(v2, v3);
            }
        }
    }

    if (OM == 3) {
        // causal column-softmax partials over this 128x128 tile
        float2* part2 = (float2*)smem;   // [128 cols][2 m-warp-groups]
#pragma unroll
        for (int nj = 0; nj < 4; ++nj) {
#pragma unroll
            for (int j = 0; j < 2; ++j) {
                int s = n0 + wn + nj * 8 + (lane & 3) * 2 + j;
                float m = -INFINITY, l = 0.f;
#pragma unroll
                for (int mi = 0; mi < 4; ++mi) {
#pragma unroll
                    for (int half = 0; half < 2; ++half) {
                        int t = m0 + wm + mi * 16 + (lane >> 2) + half * 8;
                        if (t >= s) {
                            float w = alpha * acc[mi][nj][half * 2 + j];
                            float nm = fmaxf(m, w);
                            l = l * __expf(m - nm) + __expf(w - nm);
                            m = nm;
                        }
                    }
                }
#pragma unroll
                for (int off = 4; off < 32; off <<= 1) {
                    float m2 = __shfl_xor_sync(0xFFFFFFFFu, m, off);
                    float l2 = __shfl_xor_sync(0xFFFFFFFFu, l, off);
                    lse_merge(m, l, m2, l2);
                }
                if ((lane >> 2) == 0) {
                    int cl = wn + nj * 8 + (lane & 3) * 2 + j;
                    part2[cl * 2 + (wid >> 2)] = make_float2(m, l);
                }
            }
        }
        __syncthreads();
        if (tid < 128) {
            float2 a0 = part2[tid * 2 + 0];
            float2 a1 = part2[tid * 2 + 1];
            float m = a0.x, l = a0.y;
            lse_merge(m, l, a1.x, a1.y);
            CP[((size_t)z * TLEN + n0 + tid) * 8 + blockIdx.y] = make_float2(m, l);
        }
    }
}

// merge 8 m-tile partials per (b, s) -> cmax, csum
__global__ void colmerge_kernel(const float2* __restrict__ CP,
                                float* __restrict__ cmax,
                                float* __restrict__ csum) {
    int i = blockIdx.x * 256 + threadIdx.x;      // 0..4095
    float m = -INFINITY, l = 0.f;
#pragma unroll
    for (int j = 0; j < 8; ++j) {
        float2 q = CP[(size_t)i * 8 + j];
        lse_merge(m, l, q.x, q.y);
    }
    cmax[i] = m;
    csum[i] = l;
}

// att = masked exp(wei - cmax)/csum -> fp16
__global__ void att_kernel(const float* __restrict__ wei,
                           const float* __restrict__ cmax,
                           const float* __restrict__ csum,
                           __half* __restrict__ af) {
    size_t i = ((size_t)blockIdx.x * blockDim.x + threadIdx.x) * 2;
    int b = (int)(i >> 20);
    int r = (int)(i & (TLEN * TLEN - 1));
    int t = r >> 10;
    int s = r & (TLEN - 1);
    float v0 = 0.f, v1 = 0.f;
    if (t >= s)
        v0 = __expf(wei[i] - cmax[b * TLEN + s]) / csum[b * TLEN + s];
    if (t >= s + 1)
        v1 = __expf(wei[i + 1] - cmax[b * TLEN + s + 1]) / csum[b * TLEN + s + 1];
    *(uint32_t*)(af + i) = pack_h2(v0, v1);
}

// ============================================================================
// lm_head fp16 MMA: 128x256 CTA tile, 256 threads, warp tile 64x64,
// 2-stage cp.async, fused loss partials
// ============================================================================
__global__ __launch_bounds__(256, 1)
void lmhead_fp16_kernel(const uint32_t* __restrict__ Ap,
                        const uint32_t* __restrict__ Bp,
                        const float* __restrict__ bias,
                        float* __restrict__ out,
                        float2* __restrict__ P) {
    extern __shared__ char smem[];
    const uint32_t sbase = smem_u32(smem);
    const int tid = threadIdx.x;
    const int wid = tid >> 5;
    const int lane = tid & 31;
    const int m0 = blockIdx.x * LM_BM;
    const int n0 = blockIdx.y * LM_BN;
    const int mt0 = m0 >> 4;
    const int nt0 = n0 >> 3;
    const int gm = wid >> 2;            // 0..1 (m half)
    const int gn = wid & 3;             // 0..3 (n quarter)
    const int wmt = gm * 4;             // 4 m16-tiles per warp
    const int wnt = gn * 8;             // 8 n8-tiles per warp

    float acc[4][8][4];
#pragma unroll
    for (int i = 0; i < 4; ++i)
#pragma unroll
        for (int j = 0; j < 8; ++j)
#pragma unroll
            for (int q = 0; q < 4; ++q) acc[i][j][q] = 0.f;

    auto issue = [&](int chunk, int stage) {
        int kt0 = chunk * 4;
        uint32_t sb = sbase + stage * LM_STAGE;
#pragma unroll
        for (int j = 0; j < 12; ++j) {
            int idx = tid + j * 256;
            if (idx < 1024) {
                int blk = idx >> 5;
                int off = (idx & 31) * 16;
                int mt_l = blk >> 2, kt_l = blk & 3;
                const void* g = (const char*)Ap
                    + (size_t)(mt0 + mt_l) * 16384 + (size_t)(kt0 + kt_l) * 512 + off;
                cp_async16(sb + blk * 512 + off, g);
            } else {
                int i2 = idx - 1024;
                int blk = i2 >> 4;
                int off = (i2 & 15) * 16;
                int nt_l = blk >> 2, kt_l = blk & 3;
                const void* g = (const char*)Bp
                    + (size_t)(nt0 + nt_l) * 8192 + (size_t)(kt0 + kt_l) * 256 + off;
                cp_async16(sb + SM_A_BYTES + blk * 256 + off, g);
            }
        }
        cp_commit();
    };

    issue(0, 0);
    issue(1, 1);

    for (int c = 0; c < LM_NCH; ++c) {
        if (c < LM_NCH - 2) cp_wait<1>(); else cp_wait<0>();
        __syncthreads();

        uint32_t sb = sbase + (c & 1) * LM_STAGE;
#pragma unroll
        for (int kt = 0; kt < 4; ++kt) {
            uint32_t af[4][4], bf[8][2];
#pragma unroll
            for (int mi = 0; mi < 4; ++mi) {
                uint32_t a = sb + ((wmt + mi) * 4 + kt) * 512 + lane * 16;
                uint4 v = *(const uint4*)(smem + (a - sbase));
                af[mi][0] = v.x; af[mi][1] = v.y; af[mi][2] = v.z; af[mi][3] = v.w;
            }
#pragma unroll
            for (int nj = 0; nj < 8; ++nj) {
                uint32_t a = sb + SM_A_BYTES + ((wnt + nj) * 4 + kt) * 256 + lane * 8;
                uint2 v = *(const uint2*)(smem + (a - sbase));
                bf[nj][0] = v.x; bf[nj][1] = v.y;
            }
#pragma unroll
            for (int mi = 0; mi < 4; ++mi)
#pragma unroll
                for (int nj = 0; nj < 8; ++nj)
                    mma16816_f16(acc[mi][nj], af[mi], bf[nj][0], bf[nj][1]);
        }
        __syncthreads();
        if (c + 2 < LM_NCH) issue(c + 2, c & 1);
    }

    // epilogue: logits + bias + per-row (max, sumexp) partials
    float2* part = (float2*)smem;       // [128 rows][4 n-warps]
#pragma unroll
    for (int mi = 0; mi < 4; ++mi) {
#pragma unroll
        for (int half = 0; half < 2; ++half) {
            int rloc = gm * 64 + mi * 16 + (lane >> 2) + half * 8;
            float* prow = out + (size_t)(m0 + rloc) * VOC;
            float m = -INFINITY, l = 0.f;
#pragma unroll
            for (int nj = 0; nj < 8; ++nj) {
                int ncol = n0 + gn * 64 + nj * 8 + (lane & 3) * 2;
                if (ncol < VOC) {
                    float x = acc[mi][nj][half * 2 + 0] + __ldg(&bias[ncol]);
                    prow[ncol] = x;
                    float nm = fmaxf(m, x);
                    l = l * __expf(m - nm) + __expf(x - nm);
                    m = nm;
                }
                if (ncol + 1 < VOC) {
                    float x = acc[mi][nj][half * 2 + 1] + __ldg(&bias[ncol + 1]);
                    prow[ncol + 1] = x;
                    float nm = fmaxf(m, x);
                    l = l * __expf(m - nm) + __expf(x - nm);
                    m = nm;
                }
            }
#pragma unroll
            for (int off = 1; off < 4; off <<= 1) {
                float m2 = __shfl_xor_sync(0xFFFFFFFFu, m, off);
                float l2 = __shfl_xor_sync(0xFFFFFFFFu, l, off);
                lse_merge(m, l, m2, l2);
            }
            if ((lane & 3) == 0)
                part[rloc * 4 + gn] = make_float2(m, l);
        }
    }
    __syncthreads();
    if (tid < 128) {
        float m = -INFINITY, l = 0.f;
#pragma unroll
        for (int j = 0; j < 4; ++j) {
            float2 q = part[tid * 4 + j];
            lse_merge(m, l, q.x, q.y);
        }
        P[(size_t)(m0 + tid) * NT_N + blockIdx.y] = make_float2(m, l);
    }
}

// ============================================================================
// Loss from partials
// ============================================================================
__global__ void rowloss_partials_kernel(const float2* __restrict__ P,
                                        const float* __restrict__ logits,
                                        const int* __restrict__ target,
                                        float* __restrict__ rowloss) {
    int row = blockIdx.x;
    const float2* p = P + (size_t)row * NT_N;
    float m = -INFINITY, l = 0.f;
    for (int j = threadIdx.x; j < NT_N; j += 128) {
        float2 q = p[j];
        lse_merge(m, l, q.x, q.y);
    }
#pragma unroll
    for (int off = 16; off; off >>= 1) {
        float m2 = __shfl_xor_sync(0xFFFFFFFFu, m, off);
        float l2 = __shfl_xor_sync(0xFFFFFFFFu, l, off);
        lse_merge(m, l, m2, l2);
    }
    __shared__ float sm[4], sl[4];
    if ((threadIdx.x & 31) == 0) { sm[threadIdx.x >> 5] = m; sl[threadIdx.x >> 5] = l; }
    __syncthreads();
    if (threadIdx.x == 0) {
        m = sm[0]; l = sl[0];
        for (int j = 1; j < 4; ++j) lse_merge(m, l, sm[j], sl[j]);
        rowloss[row] = m + logf(l) - logits[(size_t)row * VOC + target[row]];
    }
}

__global__ void loss_reduce_kernel(const float* __restrict__ rowloss,
                                   float* __restrict__ out) {
    __shared__ float s[256];
    float acc = 0.f;
    for (int j = threadIdx.x; j < MALL; j += 256) acc += rowloss[j];
    s[threadIdx.x] = acc;
    __syncthreads();
    for (int o = 128; o; o >>= 1) {
        if (threadIdx.x < o) s[threadIdx.x] += s[threadIdx.x + o];
        __syncthreads();
    }
    if (threadIdx.x == 0) *out = s[0] / (float)MALL;
}

// ============================================================================
extern "C" void kernel_launch(void* const* d_in, const int* in_sizes, int n_in,
                              void* d_out, int out_size) {
    const int*   idx    = (const int*)d_in[0];
    const int*   target = (const int*)d_in[1];
    const float* tok    = (const float*)d_in[2];
    const float* pos    = (const float*)d_in[3];
    const float* Wk     = (const float*)d_in[4];
    const float* Wq     = (const float*)d_in[5];
    const float* Wv     = (const float*)d_in[6];
    const float* Wlm    = (const float*)d_in[7];
    const float* blm    = (const float*)d_in[8];
    float* out = (float*)d_out;

    __half *Xf, *Wtf, *KQVf, *Vtf, *ATTf;
    float *WEI, *cmax, *csum, *rl;
    uint32_t *Ap, *Bp;
    float2 *P, *CP;
    cudaGetSymbolAddress((void**)&Xf,   g_Xf);
    cudaGetSymbolAddress((void**)&Wtf,  g_Wtf);
    cudaGetSymbolAddress((void**)&KQVf, g_KQVf);
    cudaGetSymbolAddress((void**)&Vtf,  g_Vtf);
    cudaGetSymbolAddress((void**)&WEI,  g_WEI);
    cudaGetSymbolAddress((void**)&ATTf, g_ATTf);
    cudaGetSymbolAddress((void**)&Ap,   g_Apack);
    cudaGetSymbolAddress((void**)&Bp,   g_Bpack);
    cudaGetSymbolAddress((void**)&cmax, g_cmax);
    cudaGetSymbolAddress((void**)&csum, g_csum);
    cudaGetSymbolAddress((void**)&rl,   g_rowloss);
    cudaGetSymbolAddress((void**)&P,    g_P);
    cudaGetSymbolAddress((void**)&CP,   g_CP);

    cudaFuncSetAttribute(lmhead_fp16_kernel,
                         cudaFuncAttributeMaxDynamicSharedMemorySize, SMEM_LM);
    cudaFuncSetAttribute(mma_f16_kernel<1>,
                         cudaFuncAttributeMaxDynamicSharedMemorySize, SMEM_F16);
    cudaFuncSetAttribute(mma_f16_kernel<2>,
                         cudaFuncAttributeMaxDynamicSharedMemorySize, SMEM_F16);
    cudaFuncSetAttribute(mma_f16_kernel<3>,
                         cudaFuncAttributeMaxDynamicSharedMemorySize, SMEM_F16);

    const float scale = 0.044194173824159216f;  // 512^-0.5 (n_embed, not head)
    const long long sME = (long long)MALL * EMB;
    const long long sTE = (long long)TLEN * EMB;
    const long long sTT = (long long)TLEN * TLEN;
    const long long sEE = (long long)EMB * EMB;

    // 0) weight preprocessing
    pack_w_kernel<<<dim3(N_PAD / 64, EMB / 64), 256>>>(Wlm, Bp);
    transpose_w_kernel<<<dim3(EMB / 32, EMB / 32, 3), dim3(32, 8)>>>(Wk, Wq, Wv, Wtf);

    // 1) embedding (fp16)
    embed_kernel<<<MALL, 128>>>(idx, tok, pos, Xf);

    // 2) [K,Q,V] = x @ W (fp16 single-pass, z-batched)
    mma_f16_kernel<1><<<dim3(EMB / BN, MALL / BM, 3), 256, SMEM_F16>>>(
        Xf, EMB, 0, Wtf, EMB, sEE, EMB / BKC, 1.f,
        nullptr, KQVf, EMB, sME, nullptr, nullptr);

    // 3) V^T per batch
    transpose_h_kernel<<<dim3(EMB / 32, TLEN / 32, BATCH), dim3(32, 8)>>>(
        KQVf + 2 * sME, Vtf, TLEN, EMB);

    // 4) wei = scale * q @ k^T with fused column-softmax partials
    mma_f16_kernel<3><<<dim3(TLEN / BN, TLEN / BM, BATCH), 256, SMEM_F16>>>(
        KQVf + 1 * sME, EMB, sTE, KQVf + 0 * sME, EMB, sTE,
        EMB / BKC, scale, WEI, nullptr, TLEN, sTT, nullptr, CP);
    colmerge_kernel<<<(BATCH * TLEN) / 256, 256>>>(CP, cmax, csum);

    // 5) att -> fp16
    att_kernel<<<(BATCH * TLEN * TLEN) / 512, 256>>>(WEI, cmax, csum, ATTf);

    // 6) O = att @ v, written directly as lm_head A-fragments
    mma_f16_kernel<2><<<dim3(EMB / BN, TLEN / BM, BATCH), 256, SMEM_F16>>>(
        ATTf, TLEN, sTT, Vtf, TLEN, sTE,
        TLEN / BKC, 1.f, nullptr, nullptr, 0, 0, Ap, nullptr);

    // 7) logits = O @ W_lm + b_lm (fp16, 256-thread 64x64 warp tile) + loss partials
    lmhead_fp16_kernel<<<dim3(MALL / LM_BM, NT_N), 256, SMEM_LM>>>(
        Ap, Bp, blm, out, P);

    // 8) loss
    rowloss_partials_kernel<<<MALL, 128>>>(P, out, target, rl);
    loss_reduce_kernel<<<1, 256>>>(rl, out + (size_t)out_size - 1);
}

// round 16
// speedup vs baseline: 1.1227x; 1.1227x over previous
#include <cuda_runtime.h>
#include <cuda_bf16.h>
#include <cuda_fp16.h>
#include <math.h>
#include <stdint.h>

// Problem constants
#define BATCH 4
#define TLEN 1024
#define EMB 512
#define VOC 50257
#define MALL (BATCH * TLEN)          // 4096 rows

// fp16 NT MMA tiling (attention path)
#define BM 128
#define BN 128
#define BKC 32                        // k per chunk (fp16) = 64B/row
#define ROWB 80                       // SMEM row stride bytes (conflict-free)
#define F16_TILE (128 * ROWB)         // 10240
#define F16_STAGE (2 * F16_TILE)      // 20480 (A + B)
#define SMEM_F16 (2 * F16_STAGE)      // 40960 -> 2 CTAs/SM

// lm_head fp16 tiling (512 threads, warp tile 64x32 — R9 known-good)
#define LM_BM 128
#define LM_BN 256
#define NT_N 197                      // ceil(50257/256)
#define N_PAD (NT_N * LM_BN)          // 50432
#define NKT (EMB / 16)                // 32 k-tiles of 16
#define LM_NCH (NKT / 4)              // 8 chunks
#define SM_A_BYTES (8 * 4 * 512)      // 16384
#define SM_B_BYTES (32 * 4 * 256)     // 32768
#define LM_STAGE (SM_A_BYTES + SM_B_BYTES)   // 49152
#define SMEM_LM (2 * LM_STAGE)        // 98304

// buffers
static __device__ __half    g_Xf[MALL * EMB];
static __device__ __half    g_Wtf[3 * EMB * EMB];        // [Wk^T,Wq^T,Wv^T] fp16
static __device__ __half    g_KQVf[3 * MALL * EMB];
static __device__ __half    g_Vtf[MALL * EMB];           // V^T per batch
static __device__ float     g_WEI[BATCH * TLEN * TLEN];
static __device__ __half    g_ATTf[BATCH * TLEN * TLEN];
static __device__ uint32_t  g_Apack[MALL * EMB / 2];     // frag-major fp16x2
static __device__ uint32_t  g_Bpack[(size_t)N_PAD * EMB / 2];
static __device__ float  g_cmax[BATCH * TLEN];
static __device__ float  g_csum[BATCH * TLEN];
static __device__ float  g_rowloss[MALL];
static __device__ float2 g_P[(size_t)MALL * NT_N];
static __device__ float2 g_CP[(size_t)BATCH * TLEN * 8]; // col-softmax partials

// ============================================================================
// PTX helpers
// ============================================================================
__device__ __forceinline__ uint32_t smem_u32(const void* p) {
    uint32_t a;
    asm("{ .reg .u64 t; cvta.to.shared.u64 t, %1; cvt.u32.u64 %0, t; }"
        : "=r"(a) : "l"(p));
    return a;
}
__device__ __forceinline__ void cp_async16(uint32_t dst, const void* src) {
    asm volatile("cp.async.cg.shared.global [%0], [%1], 16;"
                 :: "r"(dst), "l"(src) : "memory");
}
__device__ __forceinline__ void cp_commit() {
    asm volatile("cp.async.commit_group;" ::: "memory");
}
template <int N>
__device__ __forceinline__ void cp_wait() {
    asm volatile("cp.async.wait_group %0;" :: "n"(N) : "memory");
}
__device__ __forceinline__ void ldm_x4(uint32_t* r, uint32_t addr) {
    asm volatile("ldmatrix.sync.aligned.m8n8.x4.shared.b16 {%0,%1,%2,%3}, [%4];"
                 : "=r"(r[0]), "=r"(r[1]), "=r"(r[2]), "=r"(r[3]) : "r"(addr));
}
__device__ __forceinline__ void mma16816_f16(float* c, const uint32_t* a,
                                             uint32_t b0, uint32_t b1) {
    asm volatile(
        "mma.sync.aligned.m16n8k16.row.col.f32.f16.f16.f32 "
        "{%0,%1,%2,%3}, {%4,%5,%6,%7}, {%8,%9}, {%0,%1,%2,%3};"
        : "+f"(c[0]), "+f"(c[1]), "+f"(c[2]), "+f"(c[3])
        : "r"(a[0]), "r"(a[1]), "r"(a[2]), "r"(a[3]), "r"(b0), "r"(b1));
}
__device__ __forceinline__ uint32_t pack_h2(float x, float y) {
    __half2 h = __floats2half2_rn(x, y);
    return *(uint32_t*)&h;
}
__device__ __forceinline__ void lse_merge(float& m, float& l, float m2, float l2) {
    if (l2 > 0.f) {
        if (l == 0.f) { m = m2; l = l2; }
        else {
            float nm = fmaxf(m, m2);
            l = l * __expf(m - nm) + l2 * __expf(m2 - nm);
            m = nm;
        }
    }
}

// ============================================================================
// Embedding: x = tok_emb[idx] + pos_emb -> fp16
// ============================================================================
__global__ void embed_kernel(const int* __restrict__ idx,
                             const float* __restrict__ tok,
                             const float* __restrict__ pos,
                             __half* __restrict__ xf) {
    int n = blockIdx.x;
    int t = n & (TLEN - 1);
    int e4 = threadIdx.x;
    int token = __ldg(&idx[n]);
    float4 a = *(const float4*)&tok[(size_t)token * EMB + e4 * 4];
    float4 p = *(const float4*)&pos[(size_t)t * EMB + e4 * 4];
    a.x += p.x; a.y += p.y; a.z += p.z; a.w += p.w;
    uint32_t* o = (uint32_t*)(xf + (size_t)n * EMB + e4 * 4);
    o[0] = pack_h2(a.x, a.y);
    o[1] = pack_h2(a.z, a.w);
}

// z-batched: fp32 W[z] [K,N] -> transposed fp16 [N,K] at out + z*EMB*EMB
__global__ void transpose_w_kernel(const float* __restrict__ W0,
                                   const float* __restrict__ W1,
                                   const float* __restrict__ W2,
                                   __half* __restrict__ out) {
    __shared__ float t[32][33];
    const float* W = (blockIdx.z == 0) ? W0 : (blockIdx.z == 1) ? W1 : W2;
    out += (size_t)blockIdx.z * EMB * EMB;
    int n0 = blockIdx.x * 32;
    int k0 = blockIdx.y * 32;
    for (int r = threadIdx.y; r < 32; r += 8)
        t[r][threadIdx.x] = W[(size_t)(k0 + r) * EMB + n0 + threadIdx.x];
    __syncthreads();
    for (int r = threadIdx.y; r < 32; r += 8)
        out[(size_t)(n0 + r) * EMB + k0 + threadIdx.x] = __float2half(t[threadIdx.x][r]);
}

// fp16 [rows, cols] -> [cols, rows] per batch z
__global__ void transpose_h_kernel(const __half* __restrict__ src,
                                   __half* __restrict__ dst,
                                   int rows, int cols) {
    __shared__ __half t[32][33];
    src += (size_t)blockIdx.z * rows * cols;
    dst += (size_t)blockIdx.z * rows * cols;
    int c0 = blockIdx.x * 32;
    int r0 = blockIdx.y * 32;
    for (int r = threadIdx.y; r < 32; r += 8)
        t[r][threadIdx.x] = src[(size_t)(r0 + r) * cols + c0 + threadIdx.x];
    __syncthreads();
    for (int r = threadIdx.y; r < 32; r += 8)
        dst[(size_t)(c0 + r) * rows + r0 + threadIdx.x] = t[threadIdx.x][r];
}

// ============================================================================
// W_lm [512, VOC] -> Bpack frag-major fp16 [nt][kt(32)][64 u32]
// ============================================================================
__global__ void pack_w_kernel(const float* __restrict__ W,
                              uint32_t* __restrict__ Bp) {
    __shared__ float t[64][65];
    int n0 = blockIdx.x * 64;
    int k0 = blockIdx.y * 64;
    int tid = threadIdx.x;
#pragma unroll
    for (int w = 0; w < 16; ++w) {
        int e = tid + w * 256;
        int kk = e >> 6, nn = e & 63;
        int n = n0 + nn;
        t[kk][nn] = (n < VOC) ? W[(size_t)(k0 + kk) * VOC + n] : 0.f;
    }
    __syncthreads();
#pragma unroll
    for (int w = 0; w < 8; ++w) {
        int f = tid + w * 256;              // 0..2047
        int blk = f >> 6, pos = f & 63;
        int bnt = blk >> 2, bkt = blk & 3;
        int lane = pos >> 1, j = pos & 1;
        int n_loc = bnt * 8 + (lane >> 2);
        int k_loc = bkt * 16 + (lane & 3) * 2 + j * 8;
        uint32_t v = pack_h2(t[k_loc][n_loc], t[k_loc + 1][n_loc]);
        size_t addr = (size_t)(n0 / 8 + bnt) * (NKT * 64)
                    + (size_t)(k0 / 16 + bkt) * 64 + pos;
        Bp[addr] = v;
    }
}

// ============================================================================
// fp16 single-pass NT MMA GEMM: C = alpha * A @ B^T
// OM=1: fp16 row-major out; OM=2: A-fragment out (to Apack)
// OM=3: fp32 out + fused causal column-softmax partials (q@k^T)
// ============================================================================
template <int OM>
__global__ __launch_bounds__(256, 2)
void mma_f16_kernel(const __half* __restrict__ A, int lda, long long sA,
                    const __half* __restrict__ B, int ldb, long long sB,
                    int nchunk, float alpha,
                    float* __restrict__ Cf, __half* __restrict__ Ch,
                    int ldc, long long sC,
                    uint32_t* __restrict__ Ap,
                    float2* __restrict__ CP) {
    extern __shared__ char smem[];
    const uint32_t sbase = smem_u32(smem);
    const int tid = threadIdx.x;
    const int wid = tid >> 5;
    const int lane = tid & 31;
    const int m0 = blockIdx.y * BM;
    const int n0 = blockIdx.x * BN;
    const int z = blockIdx.z;
    const int wm = (wid >> 2) * 64;
    const int wn = (wid & 3) * 32;

    const __half* srcA = A + (long long)z * sA + (size_t)m0 * lda;
    const __half* srcB = B + (long long)z * sB + (size_t)n0 * ldb;

    float acc[4][4][4];
#pragma unroll
    for (int i = 0; i < 4; ++i)
#pragma unroll
        for (int j = 0; j < 4; ++j)
#pragma unroll
            for (int q = 0; q < 4; ++q) acc[i][j][q] = 0.f;

    auto issue = [&](int chunk, int stage) {
#pragma unroll
        for (int j = 0; j < 4; ++j) {
            int idx = tid + j * 256;
            int t = idx >> 9;                  // 0=A, 1=B
            int r = (idx >> 2) & 127;
            int c = idx & 3;
            const __half* s = (t == 0)
                ? srcA + (size_t)r * lda + chunk * BKC + c * 8
                : srcB + (size_t)r * ldb + chunk * BKC + c * 8;
            uint32_t d = sbase + stage * F16_STAGE + t * F16_TILE + r * ROWB + c * 16;
            cp_async16(d, s);
        }
        cp_commit();
    };

    issue(0, 0);
    if (nchunk > 1) issue(1, 1);

    const int lrow = lane & 15;
    const int lcolhalf = (lane >> 4) * 16;

    for (int c = 0; c < nchunk; ++c) {
        if (c + 2 < nchunk) cp_wait<1>(); else cp_wait<0>();
        __syncthreads();

        uint32_t stg = sbase + (c & 1) * F16_STAGE;
#pragma unroll
        for (int ks = 0; ks < 2; ++ks) {
            uint32_t kb = ks * 32 + lcolhalf;
            uint32_t aF[4][4], bF[2][4];
#pragma unroll
            for (int mi = 0; mi < 4; ++mi)
                ldm_x4(aF[mi], stg + (wm + mi * 16 + lrow) * ROWB + kb);
#pragma unroll
            for (int g = 0; g < 2; ++g)
                ldm_x4(bF[g], stg + F16_TILE + (wn + g * 16 + lrow) * ROWB + kb);
#pragma unroll
            for (int mi = 0; mi < 4; ++mi)
#pragma unroll
                for (int nj = 0; nj < 4; ++nj) {
                    int g = nj >> 1, p = nj & 1;
                    mma16816_f16(acc[mi][nj], aF[mi], bF[g][p], bF[g][p + 2]);
                }
        }
        __syncthreads();
        if (c + 2 < nchunk) issue(c + 2, c & 1);
    }

#pragma unroll
    for (int mi = 0; mi < 4; ++mi) {
#pragma unroll
        for (int nj = 0; nj < 4; ++nj) {
            float v0 = alpha * acc[mi][nj][0];
            float v1 = alpha * acc[mi][nj][1];
            float v2 = alpha * acc[mi][nj][2];
            float v3 = alpha * acc[mi][nj][3];
            int mrow = m0 + wm + mi * 16 + (lane >> 2);
            int ncol = n0 + wn + nj * 8 + (lane & 3) * 2;
            if (OM == 3) {
                size_t o0 = (size_t)((long long)z * sC) + (size_t)mrow * ldc + ncol;
                *(float2*)(Cf + o0) = make_float2(v0, v1);
                *(float2*)(Cf + o0 + (size_t)8 * ldc) = make_float2(v2, v3);
            } else if (OM == 1) {
                size_t o0 = (size_t)((long long)z * sC) + (size_t)mrow * ldc + ncol;
                *(uint32_t*)(Ch + o0) = pack_h2(v0, v1);
                *(uint32_t*)(Ch + o0 + (size_t)8 * ldc) = pack_h2(v2, v3);
            } else if (OM == 2) {
                int mt = (z * TLEN + mrow - (lane >> 2)) >> 4;
                int col = n0 + wn + nj * 8;
                int kt = col >> 4;
                int jh = (col >> 3) & 1;
                size_t base = (size_t)mt * 4096 + (size_t)kt * 128 + lane * 4 + jh * 2;
                Ap[base + 0] = pack_h2(v0, v1);
                Ap[base + 1] = pack_h2(v2, v3);
            }
        }
    }

    if (OM == 3) {
        // causal column-softmax partials over this 128x128 tile
        float2* part2 = (float2*)smem;   // [128 cols][2 m-warp-groups]
#pragma unroll
        for (int nj = 0; nj < 4; ++nj) {
#pragma unroll
            for (int j = 0; j < 2; ++j) {
                int s = n0 + wn + nj * 8 + (lane & 3) * 2 + j;
                float m = -INFINITY, l = 0.f;
#pragma unroll
                for (int mi = 0; mi < 4; ++mi) {
#pragma unroll
                    for (int half = 0; half < 2; ++half) {
                        int t = m0 + wm + mi * 16 + (lane >> 2) + half * 8;
                        if (t >= s) {
                            float w = alpha * acc[mi][nj][half * 2 + j];
                            float nm = fmaxf(m, w);
                            l = l * __expf(m - nm) + __expf(w - nm);
                            m = nm;
                        }
                    }
                }
#pragma unroll
                for (int off = 4; off < 32; off <<= 1) {
                    float m2 = __shfl_xor_sync(0xFFFFFFFFu, m, off);
                    float l2 = __shfl_xor_sync(0xFFFFFFFFu, l, off);
                    lse_merge(m, l, m2, l2);
                }
                if ((lane >> 2) == 0) {
                    int cl = wn + nj * 8 + (lane & 3) * 2 + j;
                    part2[cl * 2 + (wid >> 2)] = make_float2(m, l);
                }
            }
        }
        __syncthreads();
        if (tid < 128) {
            float2 a0 = part2[tid * 2 + 0];
            float2 a1 = part2[tid * 2 + 1];
            float m = a0.x, l = a0.y;
            lse_merge(m, l, a1.x, a1.y);
            CP[((size_t)z * TLEN + n0 + tid) * 8 + blockIdx.y] = make_float2(m, l);
        }
    }
}

// merge 8 m-tile partials per (b, s) -> cmax, csum
__global__ void colmerge_kernel(const float2* __restrict__ CP,
                                float* __restrict__ cmax,
                                float* __restrict__ csum) {
    int i = blockIdx.x * 256 + threadIdx.x;      // 0..4095
    float m = -INFINITY, l = 0.f;
#pragma unroll
    for (int j = 0; j < 8; ++j) {
        float2 q = CP[(size_t)i * 8 + j];
        lse_merge(m, l, q.x, q.y);
    }
    cmax[i] = m;
    csum[i] = l;
}

// att = masked exp(wei - cmax)/csum -> fp16
__global__ void att_kernel(const float* __restrict__ wei,
                           const float* __restrict__ cmax,
                           const float* __restrict__ csum,
                           __half* __restrict__ af) {
    size_t i = ((size_t)blockIdx.x * blockDim.x + threadIdx.x) * 2;
    int b = (int)(i >> 20);
    int r = (int)(i & (TLEN * TLEN - 1));
    int t = r >> 10;
    int s = r & (TLEN - 1);
    float v0 = 0.f, v1 = 0.f;
    if (t >= s)
        v0 = __expf(wei[i] - cmax[b * TLEN + s]) / csum[b * TLEN + s];
    if (t >= s + 1)
        v1 = __expf(wei[i + 1] - cmax[b * TLEN + s + 1]) / csum[b * TLEN + s + 1];
    *(uint32_t*)(af + i) = pack_h2(v0, v1);
}

// ============================================================================
// lm_head fp16 MMA: 128x256 CTA tile, 512 threads, warp tile 64x32 (R9 config),
// 2-stage cp.async, fused loss partials
// ============================================================================
__global__ __launch_bounds__(512, 1)
void lmhead_fp16_kernel(const uint32_t* __restrict__ Ap,
                        const uint32_t* __restrict__ Bp,
                        const float* __restrict__ bias,
                        float* __restrict__ out,
                        float2* __restrict__ P) {
    extern __shared__ char smem[];
    const uint32_t sbase = smem_u32(smem);
    const int tid = threadIdx.x;
    const int wid = tid >> 5;
    const int lane = tid & 31;
    const int m0 = blockIdx.x * LM_BM;
    const int n0 = blockIdx.y * LM_BN;
    const int mt0 = m0 >> 4;
    const int nt0 = n0 >> 3;
    const int wmt = (wid >> 3) * 4;
    const int wnt = (wid & 7) * 4;

    float acc[4][4][4];
#pragma unroll
    for (int i = 0; i < 4; ++i)
#pragma unroll
        for (int j = 0; j < 4; ++j)
#pragma unroll
            for (int q = 0; q < 4; ++q) acc[i][j][q] = 0.f;

    auto issue = [&](int chunk, int stage) {
        int kt0 = chunk * 4;
        uint32_t sb = sbase + stage * LM_STAGE;
#pragma unroll
        for (int j = 0; j < 6; ++j) {
            int idx = tid + j * 512;
            if (idx < 1024) {
                int blk = idx >> 5;
                int off = (idx & 31) * 16;
                int mt_l = blk >> 2, kt_l = blk & 3;
                const void* g = (const char*)Ap
                    + (size_t)(mt0 + mt_l) * 16384 + (size_t)(kt0 + kt_l) * 512 + off;
                cp_async16(sb + blk * 512 + off, g);
            } else {
                int i2 = idx - 1024;
                int blk = i2 >> 4;
                int off = (i2 & 15) * 16;
                int nt_l = blk >> 2, kt_l = blk & 3;
                const void* g = (const char*)Bp
                    + (size_t)(nt0 + nt_l) * 8192 + (size_t)(kt0 + kt_l) * 256 + off;
                cp_async16(sb + SM_A_BYTES + blk * 256 + off, g);
            }
        }
        cp_commit();
    };

    issue(0, 0);
    issue(1, 1);

    for (int c = 0; c < LM_NCH; ++c) {
        if (c < LM_NCH - 2) cp_wait<1>(); else cp_wait<0>();
        __syncthreads();

        uint32_t sb = sbase + (c & 1) * LM_STAGE;
#pragma unroll
        for (int kt = 0; kt < 4; ++kt) {
            uint32_t af[4][4], bf[4][2];
#pragma unroll
            for (int mi = 0; mi < 4; ++mi) {
                uint32_t a = sb + ((wmt + mi) * 4 + kt) * 512 + lane * 16;
                uint4 v = *(const uint4*)(smem + (a - sbase));
                af[mi][0] = v.x; af[mi][1] = v.y; af[mi][2] = v.z; af[mi][3] = v.w;
            }
#pragma unroll
            for (int nj = 0; nj < 4; ++nj) {
                uint32_t a = sb + SM_A_BYTES + ((wnt + nj) * 4 + kt) * 256 + lane * 8;
                uint2 v = *(const uint2*)(smem + (a - sbase));
                bf[nj][0] = v.x; bf[nj][1] = v.y;
            }
#pragma unroll
            for (int mi = 0; mi < 4; ++mi)
#pragma unroll
                for (int nj = 0; nj < 4; ++nj)
                    mma16816_f16(acc[mi][nj], af[mi], bf[nj][0], bf[nj][1]);
        }
        __syncthreads();
        if (c + 2 < LM_NCH) issue(c + 2, c & 1);
    }

    // epilogue: logits + bias + per-row (max, sumexp) partials
    float2* part = (float2*)smem;   // [128][8]
#pragma unroll
    for (int mi = 0; mi < 4; ++mi) {
#pragma unroll
        for (int half = 0; half < 2; ++half) {
            int rloc = (wid >> 3) * 64 + mi * 16 + (lane >> 2) + half * 8;
            float* prow = out + (size_t)(m0 + rloc) * VOC;
            float m = -INFINITY, l = 0.f;
#pragma unroll
            for (int nj = 0; nj < 4; ++nj) {
                int ncol = n0 + (wid & 7) * 32 + nj * 8 + (lane & 3) * 2;
                if (ncol < VOC) {
                    float x = acc[mi][nj][half * 2 + 0] + __ldg(&bias[ncol]);
                    prow[ncol] = x;
                    float nm = fmaxf(m, x);
                    l = l * __expf(m - nm) + __expf(x - nm);
                    m = nm;
                }
                if (ncol + 1 < VOC) {
                    float x = acc[mi][nj][half * 2 + 1] + __ldg(&bias[ncol + 1]);
                    prow[ncol + 1] = x;
                    float nm = fmaxf(m, x);
                    l = l * __expf(m - nm) + __expf(x - nm);
                    m = nm;
                }
            }
#pragma unroll
            for (int off = 1; off < 4; off <<= 1) {
                float m2 = __shfl_xor_sync(0xFFFFFFFFu, m, off);
                float l2 = __shfl_xor_sync(0xFFFFFFFFu, l, off);
                lse_merge(m, l, m2, l2);
            }
            if ((lane & 3) == 0)
                part[rloc * 8 + (wid & 7)] = make_float2(m, l);
        }
    }
    __syncthreads();
    if (tid < 128) {
        float m = -INFINITY, l = 0.f;
#pragma unroll
        for (int j = 0; j < 8; ++j) {
            float2 q = part[tid * 8 + j];
            lse_merge(m, l, q.x, q.y);
        }
        P[(size_t)(m0 + tid) * NT_N + blockIdx.y] = make_float2(m, l);
    }
}

// ============================================================================
// Loss from partials
// ============================================================================
__global__ void rowloss_partials_kernel(const float2* __restrict__ P,
                                        const float* __restrict__ logits,
                                        const int* __restrict__ target,
                                        float* __restrict__ rowloss) {
    int row = blockIdx.x;
    const float2* p = P + (size_t)row * NT_N;
    float m = -INFINITY, l = 0.f;
    for (int j = threadIdx.x; j < NT_N; j += 128) {
        float2 q = p[j];
        lse_merge(m, l, q.x, q.y);
    }
#pragma unroll
    for (int off = 16; off; off >>= 1) {
        float m2 = __shfl_xor_sync(0xFFFFFFFFu, m, off);
        float l2 = __shfl_xor_sync(0xFFFFFFFFu, l, off);
        lse_merge(m, l, m2, l2);
    }
    __shared__ float sm[4], sl[4];
    if ((threadIdx.x & 31) == 0) { sm[threadIdx.x >> 5] = m; sl[threadIdx.x >> 5] = l; }
    __syncthreads();
    if (threadIdx.x == 0) {
        m = sm[0]; l = sl[0];
        for (int j = 1; j < 4; ++j) lse_merge(m, l, sm[j], sl[j]);
        rowloss[row] = m + logf(l) - logits[(size_t)row * VOC + target[row]];
    }
}

__global__ void loss_reduce_kernel(const float* __restrict__ rowloss,
                                   float* __restrict__ out) {
    __shared__ float s[256];
    float acc = 0.f;
    for (int j = threadIdx.x; j < MALL; j += 256) acc += rowloss[j];
    s[threadIdx.x] = acc;
    __syncthreads();
    for (int o = 128; o; o >>= 1) {
        if (threadIdx.x < o) s[threadIdx.x] += s[threadIdx.x + o];
        __syncthreads();
    }
    if (threadIdx.x == 0) *out = s[0] / (float)MALL;
}

// ============================================================================
extern "C" void kernel_launch(void* const* d_in, const int* in_sizes, int n_in,
                              void* d_out, int out_size) {
    const int*   idx    = (const int*)d_in[0];
    const int*   target = (const int*)d_in[1];
    const float* tok    = (const float*)d_in[2];
    const float* pos    = (const float*)d_in[3];
    const float* Wk     = (const float*)d_in[4];
    const float* Wq     = (const float*)d_in[5];
    const float* Wv     = (const float*)d_in[6];
    const float* Wlm    = (const float*)d_in[7];
    const float* blm    = (const float*)d_in[8];
    float* out = (float*)d_out;

    __half *Xf, *Wtf, *KQVf, *Vtf, *ATTf;
    float *WEI, *cmax, *csum, *rl;
    uint32_t *Ap, *Bp;
    float2 *P, *CP;
    cudaGetSymbolAddress((void**)&Xf,   g_Xf);
    cudaGetSymbolAddress((void**)&Wtf,  g_Wtf);
    cudaGetSymbolAddress((void**)&KQVf, g_KQVf);
    cudaGetSymbolAddress((void**)&Vtf,  g_Vtf);
    cudaGetSymbolAddress((void**)&WEI,  g_WEI);
    cudaGetSymbolAddress((void**)&ATTf, g_ATTf);
    cudaGetSymbolAddress((void**)&Ap,   g_Apack);
    cudaGetSymbolAddress((void**)&Bp,   g_Bpack);
    cudaGetSymbolAddress((void**)&cmax, g_cmax);
    cudaGetSymbolAddress((void**)&csum, g_csum);
    cudaGetSymbolAddress((void**)&rl,   g_rowloss);
    cudaGetSymbolAddress((void**)&P,    g_P);
    cudaGetSymbolAddress((void**)&CP,   g_CP);

    cudaFuncSetAttribute(lmhead_fp16_kernel,
                         cudaFuncAttributeMaxDynamicSharedMemorySize, SMEM_LM);
    cudaFuncSetAttribute(mma_f16_kernel<1>,
                         cudaFuncAttributeMaxDynamicSharedMemorySize, SMEM_F16);
    cudaFuncSetAttribute(mma_f16_kernel<2>,
                         cudaFuncAttributeMaxDynamicSharedMemorySize, SMEM_F16);
    cudaFuncSetAttribute(mma_f16_kernel<3>,
                         cudaFuncAttributeMaxDynamicSharedMemorySize, SMEM_F16);

    const float scale = 0.044194173824159216f;  // 512^-0.5 (n_embed, not head)
    const long long sME = (long long)MALL * EMB;
    const long long sTE = (long long)TLEN * EMB;
    const long long sTT = (long long)TLEN * TLEN;
    const long long sEE = (long long)EMB * EMB;

    // 0) weight preprocessing
    pack_w_kernel<<<dim3(N_PAD / 64, EMB / 64), 256>>>(Wlm, Bp);
    transpose_w_kernel<<<dim3(EMB / 32, EMB / 32, 3), dim3(32, 8)>>>(Wk, Wq, Wv, Wtf);

    // 1) embedding (fp16)
    embed_kernel<<<MALL, 128>>>(idx, tok, pos, Xf);

    // 2) [K,Q,V] = x @ W (fp16 single-pass, z-batched)
    mma_f16_kernel<1><<<dim3(EMB / BN, MALL / BM, 3), 256, SMEM_F16>>>(
        Xf, EMB, 0, Wtf, EMB, sEE, EMB / BKC, 1.f,
        nullptr, KQVf, EMB, sME, nullptr, nullptr);

    // 3) V^T per batch
    transpose_h_kernel<<<dim3(EMB / 32, TLEN / 32, BATCH), dim3(32, 8)>>>(
        KQVf + 2 * sME, Vtf, TLEN, EMB);

    // 4) wei = scale * q @ k^T with fused column-softmax partials
    mma_f16_kernel<3><<<dim3(TLEN / BN, TLEN / BM, BATCH), 256, SMEM_F16>>>(
        KQVf + 1 * sME, EMB, sTE, KQVf + 0 * sME, EMB, sTE,
        EMB / BKC, scale, WEI, nullptr, TLEN, sTT, nullptr, CP);
    colmerge_kernel<<<(BATCH * TLEN) / 256, 256>>>(CP, cmax, csum);

    // 5) att -> fp16
    att_kernel<<<(BATCH * TLEN * TLEN) / 512, 256>>>(WEI, cmax, csum, ATTf);

    // 6) O = att @ v, written directly as lm_head A-fragments
    mma_f16_kernel<2><<<dim3(EMB / BN, TLEN / BM, BATCH), 256, SMEM_F16>>>(
        ATTf, TLEN, sTT, Vtf, TLEN, sTE,
        TLEN / BKC, 1.f, nullptr, nullptr, 0, 0, Ap, nullptr);

    // 7) logits = O @ W_lm + b_lm (fp16, 512-thread 64x32 warp tile) + loss partials
    lmhead_fp16_kernel<<<dim3(MALL / LM_BM, NT_N), 512, SMEM_LM>>>(
        Ap, Bp, blm, out, P);

    // 8) loss
    rowloss_partials_kernel<<<MALL, 128>>>(P, out, target, rl);
    loss_reduce_kernel<<<1, 256>>>(rl, out + (size_t)out_size - 1);
}